// round 8
// baseline (speedup 1.0000x reference)
#include <cuda_runtime.h>
#include <cstdint>

// WindowEmbedding forward: out[b, t, k*D + d] = (t-k >= 0) ? in[b, t-k, d] : 0
// B=16, T=2048, D=256, W=7.
// R7: 256-bit (v8.f32) loads/stores — the last untested SM-side knob.
// Five prior structures all pinned at ~40us / ~5.2 TB/s => DRAM write ceiling.
// This halves store wavefronts; flat result = roofline confirmed.

#define B_DIM 16
#define T_DIM 2048
#define D_DIM 256          // floats per input row
#define W_DIM 7

#define D8 32                         // 32B (8-float) units per input row
#define SLICE_F (W_DIM * D_DIM)       // 1792 floats per output row
#define TILE_T 8                      // t-values per thread
#define NTHREADS (W_DIM * D8)         // 224

__device__ __forceinline__ void ldg_v8(const float* p, float* v) {
    asm("ld.global.nc.v8.f32 {%0,%1,%2,%3,%4,%5,%6,%7}, [%8];"
        : "=f"(v[0]), "=f"(v[1]), "=f"(v[2]), "=f"(v[3]),
          "=f"(v[4]), "=f"(v[5]), "=f"(v[6]), "=f"(v[7])
        : "l"(p));
}

__device__ __forceinline__ void stg_cs_v8(float* p, const float* v) {
    asm volatile("st.global.cs.v8.f32 [%0], {%1,%2,%3,%4,%5,%6,%7,%8};"
                 :: "l"(p),
                    "f"(v[0]), "f"(v[1]), "f"(v[2]), "f"(v[3]),
                    "f"(v[4]), "f"(v[5]), "f"(v[6]), "f"(v[7])
                 : "memory");
}

__global__ __launch_bounds__(NTHREADS) void window_embed_kernel(
    const float* __restrict__ in,    // [B, T, 256]
    float* __restrict__ out)         // [B, T, 1792]
{
    const int bt0 = blockIdx.x * TILE_T;     // b*T + t0, t0 multiple of 8
    const int t0  = bt0 & (T_DIM - 1);
    const int tid = threadIdx.x;             // 0..223
    const int k   = tid >> 5;                // shift 0..6
    const int d8  = tid & 31;                // 32B column

    const float* src = in  + (long long)(bt0 - k) * D_DIM + d8 * 8;
    float*       dst = out + (long long)bt0 * SLICE_F + k * D_DIM + d8 * 8;

    if (t0 != 0) {
        // Fast path (4080/4096 blocks): t0 >= 8 > k, all sources valid.
        #pragma unroll
        for (int jb = 0; jb < TILE_T; jb += 4) {
            float v[4][8];
            #pragma unroll
            for (int j = 0; j < 4; j++)
                ldg_v8(src + (jb + j) * D_DIM, v[j]);
            #pragma unroll
            for (int j = 0; j < 4; j++)
                stg_cs_v8(dst + (jb + j) * SLICE_F, v[j]);
        }
    } else {
        // t0 == 0: zero-fill where t - k < 0.
        #pragma unroll
        for (int jb = 0; jb < TILE_T; jb += 4) {
            float v[4][8];
            #pragma unroll
            for (int j = 0; j < 4; j++) {
                if (jb + j - k >= 0) {
                    ldg_v8(src + (jb + j) * D_DIM, v[j]);
                } else {
                    #pragma unroll
                    for (int e = 0; e < 8; e++) v[j][e] = 0.f;
                }
            }
            #pragma unroll
            for (int j = 0; j < 4; j++)
                stg_cs_v8(dst + (jb + j) * SLICE_F, v[j]);
        }
    }
}

extern "C" void kernel_launch(void* const* d_in, const int* in_sizes, int n_in,
                              void* d_out, int out_size)
{
    const float* in = (const float*)d_in[0];
    float* out = (float*)d_out;

    dim3 grid(B_DIM * T_DIM / TILE_T);   // 4096
    dim3 block(NTHREADS);                // 224
    window_embed_kernel<<<grid, block>>>(in, out);
}

// round 10
// speedup vs baseline: 1.1042x; 1.1042x over previous
#include <cuda_runtime.h>

// WindowEmbedding forward: out[b, t, k*D + d] = (t-k >= 0) ? in[b, t-k, d] : 0
// B=16, T=2048, D=256, W=7.
// R9 (converged, fixed): R5 structure — fastest measured (kernel 39.6us) —
// with SIGNED 32-bit offsets (R8's unsigned wrap zero-extended into a 64GB
// OOB pointer; signed offsets sign-extend like R5's long long and valid lanes
// land back in range). Six structures all pinned at 5.0-5.3 TB/s HBM with no
// SM resource saturated: DRAM pure-write ceiling; 235 MB output irreducible;
// ~39.5us practical floor.

#define B_DIM 16
#define T_DIM 2048
#define D_DIM 256
#define W_DIM 7

#define D4 (D_DIM / 4)          // 64 float4 per input row
#define SLICE4 (W_DIM * D4)     // 448 float4 per output row
#define TILE_T 8                // t-values per thread

__global__ __launch_bounds__(SLICE4) void window_embed_kernel(
    const float4* __restrict__ in,   // [B, T, 64] float4
    float4* __restrict__ out)        // [B, T, 448] float4
{
    const int bt0 = blockIdx.x * TILE_T;     // base (b*T + t0), t0 multiple of 8
    const int t0  = bt0 & (T_DIM - 1);
    const int tid = threadIdx.x;             // 0..447
    const int k   = tid >> 6;                // shift 0..6
    const int d4  = tid & 63;                // float4 column

    // Signed 32-bit offsets: max magnitude ~14.7M, sign-extends correctly
    // for the (rare) bt0 - k < 0 base in block 0.
    const int soff = (bt0 - k) * D4 + d4;    // may be slightly negative
    const int doff = bt0 * SLICE4 + tid;

    const float4* src = in  + soff;          // OOB base only when t0==0, k>0;
    float4*       dst = out + doff;          //   never dereferenced there.

    float4 v[TILE_T];

    if (t0 != 0) {
        // Fast path (4080/4096 blocks): t0 >= 8 > k, all sources valid.
        #pragma unroll
        for (int j = 0; j < TILE_T; j++)
            v[j] = src[j * D4];
        #pragma unroll
        for (int j = 0; j < TILE_T; j++)
            __stcs(&dst[j * SLICE4], v[j]);
    } else {
        // t0 == 0: zero-fill where t - k < 0.
        #pragma unroll
        for (int j = 0; j < TILE_T; j++) {
            const int ts = j - k;
            v[j] = (ts >= 0) ? src[j * D4] : make_float4(0.f, 0.f, 0.f, 0.f);
        }
        #pragma unroll
        for (int j = 0; j < TILE_T; j++)
            __stcs(&dst[j * SLICE4], v[j]);
    }
}

extern "C" void kernel_launch(void* const* d_in, const int* in_sizes, int n_in,
                              void* d_out, int out_size)
{
    const float4* in = (const float4*)d_in[0];
    float4* out = (float4*)d_out;

    dim3 grid(B_DIM * T_DIM / TILE_T);   // 4096
    dim3 block(SLICE4);                  // 448
    window_embed_kernel<<<grid, block>>>(in, out);
}